// round 2
// baseline (speedup 1.0000x reference)
#include <cuda_runtime.h>
#include <cstdint>

// ---------------------------------------------------------------------------
// ResidualVectorQuantizer: B=32, T=2048, D=256, K=1024, NC=8
// N = B*T = 65536 rows.
// Outputs (inferred): quantized [N*D] f32, indices [N*NC] as f32, loss [1] f32
// ---------------------------------------------------------------------------

#define NROWS   65536
#define DDIM    256
#define KCB     1024
#define NCB     8
#define MT      128      // rows per block
#define NT      64       // codewords per chunk
#define NTHREADS 512
#define RSTRIDE 260      // padded row stride (floats) for R tile
#define NCHUNK  (KCB / NT)   // 16
#define NBLOCKS (NROWS / MT) // 512

// -------- device scratch (static allocation: no cudaMalloc allowed) --------
__device__ float  g_res[(size_t)NROWS * DDIM];   // 64 MB residual buffer
__device__ float  g_WT [(size_t)NCB * DDIM * KCB]; // 8 MB transposed codebooks [c][d][k]
__device__ float  g_ww [NCB * KCB];              // ||w||^2 per codeword
__device__ double g_lp [NCB * NBLOCKS];          // per-(stage,block) loss partials

// -------- shared memory layout (in floats) --------
#define SM_RT    0
#define SM_WT    (MT * RSTRIDE)               // 33280
#define SM_RR    (SM_WT + DDIM * NT)          // 49664
#define SM_WWS   (SM_RR + MT)                 // 49792
#define SM_BVAL  (SM_WWS + NT)                // 49856
#define SM_BIDX  (SM_BVAL + MT * 16)          // 51904
#define SM_QS    (SM_BIDX + MT * 16)          // 53952
#define SM_SIDX  (SM_QS + MT * 4)             // 54464
#define SM_LP    (SM_SIDX + MT)               // 54592
#define SM_TOTALF (SM_LP + 16)                // 54608 floats
#define SMEM_BYTES (SM_TOTALF * 4)            // 218432 bytes

// ---------------------------------------------------------------------------
// Transpose codebooks [c][k][d] -> g_WT [c][d][k]  (once per launch)
// ---------------------------------------------------------------------------
__global__ void rvq_transpose_kernel(const float* __restrict__ cb)
{
    __shared__ float tile[32][33];
    const int c  = blockIdx.z;
    const int d0 = blockIdx.x * 32;   // gridDim.x = DDIM/32 = 8
    const int k0 = blockIdx.y * 32;   // gridDim.y = KCB/32 = 32
    const float* src = cb + (size_t)c * KCB * DDIM;
    float* dst = g_WT + (size_t)c * DDIM * KCB;
    const int x = threadIdx.x;        // 0..31
    for (int r = threadIdx.y; r < 32; r += 8)
        tile[r][x] = src[(size_t)(k0 + r) * DDIM + d0 + x];
    __syncthreads();
    for (int r = threadIdx.y; r < 32; r += 8)
        dst[(size_t)(d0 + r) * KCB + k0 + x] = tile[x][r];
}

// ---------------------------------------------------------------------------
// ||w||^2 per codeword: one warp per codeword (8192 codewords)
// ---------------------------------------------------------------------------
__global__ void rvq_ww_kernel(const float* __restrict__ cb)
{
    const int warp = threadIdx.x >> 5;
    const int lane = threadIdx.x & 31;
    const int k = blockIdx.x * 8 + warp;           // grid 1024 * 8 warps = 8192
    const float* w = cb + (size_t)k * DDIM;
    float s = 0.f;
    #pragma unroll
    for (int t = 0; t < 8; t++) {
        float v = w[lane + 32 * t];
        s = fmaf(v, v, s);
    }
    #pragma unroll
    for (int o = 16; o; o >>= 1) s += __shfl_down_sync(0xffffffffu, s, o);
    if (lane == 0) g_ww[k] = s;
}

// ---------------------------------------------------------------------------
// Fused per-stage kernel: scores + argmin + residual/quantized update + loss
// ---------------------------------------------------------------------------
__global__ void __launch_bounds__(NTHREADS, 1)
rvq_stage_kernel(const float* __restrict__ z,
                 const float* __restrict__ cb,
                 float* __restrict__ qOut,
                 float* __restrict__ idxOut,   // may be null
                 int c)
{
    extern __shared__ float sm[];
    float* Rt   = sm + SM_RT;
    float* Wt   = sm + SM_WT;
    float* rr   = sm + SM_RR;
    float* wws  = sm + SM_WWS;
    float* bval = sm + SM_BVAL;
    int*   bidx = (int*)(sm + SM_BIDX);
    float* qs   = sm + SM_QS;
    int*   sIdx = (int*)(sm + SM_SIDX);
    float* lp   = sm + SM_LP;

    const int tid = threadIdx.x;
    const int tx  = tid & 15;      // col group (4 codewords)
    const int ty  = tid >> 4;      // row group (4 rows), 0..31
    const int blk = blockIdx.x;
    const long long rowbase = (long long)blk * MT;

    const float* resIn = (c == 0) ? z : g_res;
    const float* wtc = g_WT + (size_t)c * DDIM * KCB;
    const float* wwc = g_ww + c * KCB;
    const float* cbc = cb + (size_t)c * KCB * DDIM;

    // ---- load R tile (coalesced, padded stride) ----
    const float4* rin = (const float4*)(resIn + rowbase * DDIM);
    #pragma unroll
    for (int l = tid; l < MT * DDIM / 4; l += NTHREADS) {
        int row = l >> 6, c4 = l & 63;
        float4 v = rin[row * 64 + c4];
        *(float4*)(Rt + row * RSTRIDE + c4 * 4) = v;
    }
    __syncthreads();

    // ---- rr = ||r||^2 per row (exact value non-critical: uniform grid shift) ----
    {
        int row = tid >> 2, qq = tid & 3;
        const float* rp = Rt + row * RSTRIDE + qq * 64;
        float s = 0.f;
        #pragma unroll
        for (int d = 0; d < 64; d++) s = fmaf(rp[d], rp[d], s);
        qs[row * 4 + qq] = s;
    }
    __syncthreads();
    if (tid < MT)
        rr[tid] = qs[tid * 4] + qs[tid * 4 + 1] + qs[tid * 4 + 2] + qs[tid * 4 + 3];

    float bestv[4] = {3.0e38f, 3.0e38f, 3.0e38f, 3.0e38f};
    int   besti[4] = {0, 0, 0, 0};

    // ---- main loop over 16 codeword chunks ----
    for (int ck = 0; ck < NCHUNK; ck++) {
        __syncthreads();   // protect Wt/wws reuse; also publishes rr on ck==0
        const int kbase = ck * NT;
        // load W chunk, already d-major in g_WT: Wt[d][k], 256x64, no padding
        #pragma unroll
        for (int l = tid; l < DDIM * NT / 4; l += NTHREADS) {
            int d = l >> 4, k4 = l & 15;
            float4 v = *(const float4*)(wtc + (size_t)d * KCB + kbase + k4 * 4);
            *(float4*)(Wt + d * NT + k4 * 4) = v;
        }
        if (tid < NT) wws[tid] = wwc[kbase + tid];
        __syncthreads();

        float acc[4][4];
        #pragma unroll
        for (int i = 0; i < 4; i++)
            #pragma unroll
            for (int j = 0; j < 4; j++) acc[i][j] = 0.f;

        const float* rbase = Rt + (ty * 4) * RSTRIDE;
        #pragma unroll 2
        for (int dv = 0; dv < 64; dv++) {
            float a[4][4];   // [row i][d sub]
            float b[4][4];   // [d sub][col j]
            #pragma unroll
            for (int i = 0; i < 4; i++)
                *(float4*)&a[i][0] = *(const float4*)(rbase + i * RSTRIDE + dv * 4);
            #pragma unroll
            for (int dd = 0; dd < 4; dd++)
                *(float4*)&b[dd][0] = *(const float4*)(Wt + (dv * 4 + dd) * NT + tx * 4);
            #pragma unroll
            for (int i = 0; i < 4; i++)
                #pragma unroll
                for (int j = 0; j < 4; j++)
                    #pragma unroll
                    for (int dd = 0; dd < 4; dd++)
                        acc[i][j] = fmaf(a[i][dd], b[dd][j], acc[i][j]);
        }

        // update per-thread argmin: d2 = fl(fl(rr - 2*dot) + ww), ties -> lowest k
        #pragma unroll
        for (int i = 0; i < 4; i++) {
            float rri = rr[ty * 4 + i];
            #pragma unroll
            for (int j = 0; j < 4; j++) {
                float t  = fmaf(-2.0f, acc[i][j], rri);  // == fl(rr - fl(2*dot))
                float d2 = t + wws[tx * 4 + j];
                int   kg = kbase + tx * 4 + j;
                if (d2 < bestv[i]) { bestv[i] = d2; besti[i] = kg; }
            }
        }
    }

    // ---- cross-thread argmin merge (lexicographic: val, then index) ----
    #pragma unroll
    for (int i = 0; i < 4; i++) {
        bval[(ty * 4 + i) * 16 + tx] = bestv[i];
        bidx[(ty * 4 + i) * 16 + tx] = besti[i];
    }
    __syncthreads();
    if (tid < MT) {
        float bv = bval[tid * 16];
        int   bi = bidx[tid * 16];
        #pragma unroll
        for (int t = 1; t < 16; t++) {
            float v = bval[tid * 16 + t];
            int  id = bidx[tid * 16 + t];
            if (v < bv || (v == bv && id < bi)) { bv = v; bi = id; }
        }
        sIdx[tid] = bi;
        if (idxOut) idxOut[(rowbase + tid) * NCB + c] = (float)bi;
    }
    __syncthreads();

    // ---- epilogue: residual / quantized update + loss partial ----
    {
        int lr = tid >> 2, qq = tid & 3;
        long long grow = rowbase + lr;
        int bi = sIdx[lr];
        const float* wrow = cbc + (size_t)bi * DDIM;
        float* ro = g_res + grow * DDIM;
        float* qo = qOut + grow * DDIM;
        float lsum = 0.f;
        #pragma unroll
        for (int t = 0; t < 16; t++) {
            int d4 = qq + 4 * t;                    // interleaved for coalescing
            float4 w4 = *(const float4*)(wrow + d4 * 4);
            float4 r4 = *(const float4*)(Rt + lr * RSTRIDE + d4 * 4);
            float4 nr;
            nr.x = r4.x - w4.x; nr.y = r4.y - w4.y;
            nr.z = r4.z - w4.z; nr.w = r4.w - w4.w;
            *(float4*)(ro + d4 * 4) = nr;
            float4 qv;
            if (c == 0) {
                qv = w4;
            } else {
                float4 qp = *(const float4*)(qo + d4 * 4);
                qv.x = qp.x + w4.x; qv.y = qp.y + w4.y;
                qv.z = qp.z + w4.z; qv.w = qp.w + w4.w;
            }
            *(float4*)(qo + d4 * 4) = qv;
            lsum = fmaf(nr.x, nr.x, lsum);
            lsum = fmaf(nr.y, nr.y, lsum);
            lsum = fmaf(nr.z, nr.z, lsum);
            lsum = fmaf(nr.w, nr.w, lsum);
        }
        #pragma unroll
        for (int o = 16; o; o >>= 1) lsum += __shfl_down_sync(0xffffffffu, lsum, o);
        if ((tid & 31) == 0) lp[tid >> 5] = lsum;
    }
    __syncthreads();
    if (tid == 0) {
        double t = 0.0;
        #pragma unroll
        for (int w = 0; w < 16; w++) t += (double)lp[w];
        g_lp[c * NBLOCKS + blk] = t;   // plain store: deterministic, no atomics
    }
}

// ---------------------------------------------------------------------------
// Final deterministic loss reduction
// ---------------------------------------------------------------------------
__global__ void rvq_loss_kernel(float* __restrict__ out, int lossOff)
{
    if (lossOff < 0) return;
    __shared__ double sd[256];
    int tid = threadIdx.x;
    double s = 0.0;
    for (int i = tid; i < NCB * NBLOCKS; i += 256) s += g_lp[i];
    sd[tid] = s;
    __syncthreads();
    for (int o = 128; o; o >>= 1) {
        if (tid < o) sd[tid] += sd[tid + o];
        __syncthreads();
    }
    if (tid == 0)
        out[lossOff] = (float)(sd[0] / (double)((long long)NROWS * DDIM));
}

// ---------------------------------------------------------------------------
extern "C" void kernel_launch(void* const* d_in, const int* in_sizes, int n_in,
                              void* d_out, int out_size)
{
    const float* z  = (const float*)d_in[0];
    const float* cb = (const float*)d_in[1];
    float* out = (float*)d_out;

    static bool attr_set = false;
    if (!attr_set) {
        cudaFuncSetAttribute(rvq_stage_kernel,
                             cudaFuncAttributeMaxDynamicSharedMemorySize,
                             SMEM_BYTES);
        attr_set = true;
    }

    const int NZ   = NROWS * DDIM;   // 16777216
    const int NIDX = NROWS * NCB;    // 524288
    float* idxOut = nullptr;
    int lossOff = -1;
    if (out_size >= NZ + NIDX + 1) { idxOut = out + NZ; lossOff = NZ + NIDX; }
    else if (out_size == NZ + NIDX) { idxOut = out + NZ; }
    else if (out_size == NZ + 1)    { lossOff = NZ; }

    {
        dim3 tb(32, 8);
        dim3 tg(DDIM / 32, KCB / 32, NCB);
        rvq_transpose_kernel<<<tg, tb>>>(cb);
    }
    rvq_ww_kernel<<<KCB * NCB / 8 / 32 * 32, 256>>>(cb);   // 1024 blocks x 8 warps

    for (int c = 0; c < NCB; c++)
        rvq_stage_kernel<<<NBLOCKS, NTHREADS, SMEM_BYTES>>>(z, cb, out, idxOut, c);

    rvq_loss_kernel<<<1, 256>>>(out, lossOff);
}

// round 6
// speedup vs baseline: 1.1257x; 1.1257x over previous
#include <cuda_runtime.h>
#include <cuda_bf16.h>
#include <cstdint>

#define NROWS 65536
#define DDIM  256
#define NCB   8
#define KCB   1024
#define BM    128
#define TPB   256
#define NBLOCKS (NROWS / BM)     // 512
#define NKT   12                 // 12 x 64 bf16 k-cols = K_ext 768

// -------- device scratch --------
__device__ float         g_res[(size_t)NROWS * DDIM];        // 64 MB
__device__ __nv_bfloat16 g_A[(size_t)NROWS * 512];           // [row][a1(256)|a2(256)]
__device__ __nv_bfloat16 g_Bs[(size_t)NCB * KCB * 512];      // [ck][b1(256)|b2(256)]
__device__ float         g_ww[NCB * KCB];
__device__ double        g_lp[NCB * NBLOCKS];

// -------- smem layout (bytes) --------
#define SO_SIDX 0        // 128 int
#define SO_RR   512      // 128 f
#define SO_QS   1024     // 256 f (reused as lp)
#define SO_WW   4096     // 1024 f
#define SO_TILE 8192     // 2 x (A 16KB + B 16KB); reused post-GEMM as cand arrays
#define SMEMB   (8192 + 65536)   // 73728

__device__ __forceinline__ uint32_t smem_u32(const void* p) {
    uint32_t a;
    asm("{ .reg .u64 t; cvta.to.shared.u64 t, %1; cvt.u32.u64 %0, t; }" : "=r"(a) : "l"(p));
    return a;
}
__device__ __forceinline__ void cp16(uint32_t dst, const void* src) {
    asm volatile("cp.async.cg.shared.global [%0], [%1], 16;" :: "r"(dst), "l"(src));
}
#define CP_COMMIT() asm volatile("cp.async.commit_group;" ::: "memory")
#define CP_WAIT(n)  asm volatile("cp.async.wait_group %0;" :: "n"(n) : "memory")

__device__ __forceinline__ void ldsm4(uint32_t* r, uint32_t addr) {
    asm volatile("ldmatrix.sync.aligned.m8n8.x4.shared.b16 {%0,%1,%2,%3}, [%4];"
        : "=r"(r[0]), "=r"(r[1]), "=r"(r[2]), "=r"(r[3]) : "r"(addr));
}
__device__ __forceinline__ void mma16816(float* d, const uint32_t* a, uint32_t b0, uint32_t b1) {
    asm volatile(
        "mma.sync.aligned.m16n8k16.row.col.f32.bf16.bf16.f32 "
        "{%0,%1,%2,%3}, {%4,%5,%6,%7}, {%8,%9}, {%0,%1,%2,%3};"
        : "+f"(d[0]), "+f"(d[1]), "+f"(d[2]), "+f"(d[3])
        : "r"(a[0]), "r"(a[1]), "r"(a[2]), "r"(a[3]), "r"(b0), "r"(b1));
}
__device__ __forceinline__ void split2(float x, __nv_bfloat16& p1, __nv_bfloat16& p2) {
    p1 = __float2bfloat16_rn(x);
    p2 = __float2bfloat16_rn(x - __bfloat162float(p1));
}
// keep sorted-ascending best-4 (lexicographic on (val, idx))
__device__ __forceinline__ void upd4(float* v, int* ix, float nv, int ni) {
    if (nv > v[3] || (nv == v[3] && ni > ix[3])) return;
    v[3] = nv; ix[3] = ni;
    #pragma unroll
    for (int p = 3; p > 0; p--) {
        bool sw = (v[p] < v[p-1]) || (v[p] == v[p-1] && ix[p] < ix[p-1]);
        if (sw) {
            float tv = v[p]; v[p] = v[p-1]; v[p-1] = tv;
            int   ti = ix[p]; ix[p] = ix[p-1]; ix[p-1] = ti;
        }
    }
}

// ---- prep kernels ----
__global__ void rvq_splitA_kernel(const float* __restrict__ z)
{
    int id = blockIdx.x * 256 + threadIdx.x;
    int row = id >> 6, d4 = id & 63;
    float4 v = *(const float4*)(z + (size_t)row * DDIM + d4 * 4);
    __nv_bfloat16 p1[4], p2[4];
    split2(v.x, p1[0], p2[0]); split2(v.y, p1[1], p2[1]);
    split2(v.z, p1[2], p2[2]); split2(v.w, p1[3], p2[3]);
    __nv_bfloat16* a = g_A + (size_t)row * 512 + d4 * 4;
    *(uint64_t*)(a)       = *(uint64_t*)p1;
    *(uint64_t*)(a + 256) = *(uint64_t*)p2;
}
__global__ void rvq_splitB_kernel(const float* __restrict__ cb)
{
    int id = blockIdx.x * 256 + threadIdx.x;
    int ck = id >> 6, d4 = id & 63;
    float4 v = *(const float4*)(cb + (size_t)ck * DDIM + d4 * 4);
    __nv_bfloat16 p1[4], p2[4];
    split2(v.x, p1[0], p2[0]); split2(v.y, p1[1], p2[1]);
    split2(v.z, p1[2], p2[2]); split2(v.w, p1[3], p2[3]);
    __nv_bfloat16* b = g_Bs + (size_t)ck * 512 + d4 * 4;
    *(uint64_t*)(b)       = *(uint64_t*)p1;
    *(uint64_t*)(b + 256) = *(uint64_t*)p2;
}
__global__ void rvq_ww_kernel(const float* __restrict__ cb)
{
    const int warp = threadIdx.x >> 5, lane = threadIdx.x & 31;
    const int k = blockIdx.x * 8 + warp;
    const float* w = cb + (size_t)k * DDIM;
    float s = 0.f;
    #pragma unroll
    for (int t = 0; t < 8; t++) { float v = w[lane + 32 * t]; s = fmaf(v, v, s); }
    #pragma unroll
    for (int o = 16; o; o >>= 1) s += __shfl_down_sync(0xffffffffu, s, o);
    if (lane == 0) g_ww[k] = s;
}

// ---- fused HMMA stage: approx GEMM filter + exact rescore ----
__global__ void __launch_bounds__(TPB)
rvq_stage_kernel(const float* __restrict__ z, const float* __restrict__ cb,
                 float* __restrict__ qOut, float* __restrict__ idxOut, int c)
{
    extern __shared__ char smc[];
    const uint32_t sb = smem_u32(smc);
    int*   sIdx = (int*)(smc + SO_SIDX);
    float* rrsh = (float*)(smc + SO_RR);
    float* qs   = (float*)(smc + SO_QS);
    float* wws  = (float*)(smc + SO_WW);

    const int tid  = threadIdx.x;
    const int lane = tid & 31;
    const int warp = tid >> 5;
    const int wr   = warp >> 1;      // 0..3 (32-row slice)
    const int wc   = warp & 1;       // 0..1 (64-col slice)
    const size_t rowbase = (size_t)blockIdx.x * BM;
    const float* resIn = (c == 0) ? z : g_res;
    const float* cbc = cb + (size_t)c * KCB * DDIM;

    for (int i = tid; i < KCB; i += TPB) wws[i] = g_ww[c * KCB + i];

    // approx rr per row (2 threads/row) — only feeds the filter
    {
        int row = tid >> 1, half = tid & 1;
        const float* rp = resIn + (rowbase + row) * DDIM + half * 128;
        float s = 0.f;
        #pragma unroll
        for (int i = 0; i < 32; i++) {
            float4 v = *(const float4*)(rp + i * 4);
            s = fmaf(v.x, v.x, s); s = fmaf(v.y, v.y, s);
            s = fmaf(v.z, v.z, s); s = fmaf(v.w, v.w, s);
        }
        qs[tid] = s;
    }
    __syncthreads();
    if (tid < BM) rrsh[tid] = qs[tid * 2] + qs[tid * 2 + 1];
    __syncthreads();

    const int g = lane >> 2;
    float rrl[4];
    #pragma unroll
    for (int mf = 0; mf < 2; mf++)
        #pragma unroll
        for (int h = 0; h < 2; h++)
            rrl[mf * 2 + h] = rrsh[wr * 32 + mf * 16 + g + 8 * h];

    // per-thread best-4 per owned row (4 rows/thread)
    float cv4[16]; int ci4[16];
    #pragma unroll
    for (int i = 0; i < 16; i++) { cv4[i] = 3.0e38f; ci4[i] = 0x7fffffff; }

    const int arow0 = wr * 32 + (lane & 15);
    const int ukA = lane >> 4;
    const int ukB = (lane >> 3) & 1;
    const int brow_in = (lane & 7) + ((lane >> 4) << 3);

    #pragma unroll 1
    for (int nb = 0; nb < 8; nb++) {
        float acc[2][8][4];
        #pragma unroll
        for (int mf = 0; mf < 2; mf++)
            #pragma unroll
            for (int j = 0; j < 8; j++)
                #pragma unroll
                for (int e = 0; e < 4; e++) acc[mf][j][e] = 0.f;

        auto prefetch = [&](int kt, int p) {
            const int aoff = ((kt & 3) * 64) + (kt >= 8 ? 256 : 0);
            const int boff = ((kt & 3) * 64) + ((kt >= 4 && kt < 8) ? 256 : 0);
            const uint32_t abase = sb + SO_TILE + p * 32768;
            const uint32_t bbase = abase + 16384;
            #pragma unroll
            for (int i = 0; i < 8; i++) {
                int v = tid + TPB * i;
                if (v < 1024) {
                    int row = v >> 3, u = v & 7;
                    const void* src = g_A + (rowbase + row) * 512 + aoff + u * 8;
                    cp16(abase + row * 128 + (((u ^ (row & 7))) << 4), src);
                } else {
                    int vb = v - 1024;
                    int nrow = vb >> 3, u = vb & 7;
                    const void* src = g_Bs + ((size_t)(c * KCB + nb * 128 + nrow)) * 512 + boff + u * 8;
                    cp16(bbase + nrow * 128 + (((u ^ (nrow & 7))) << 4), src);
                }
            }
        };

        prefetch(0, 0); CP_COMMIT();
        #pragma unroll 1
        for (int kt = 0; kt < NKT; kt++) {
            const int p = kt & 1;
            if (kt + 1 < NKT) { prefetch(kt + 1, (kt + 1) & 1); CP_COMMIT(); CP_WAIT(1); }
            else              { CP_WAIT(0); }
            __syncthreads();
            const uint32_t abase = sb + SO_TILE + p * 32768;
            const uint32_t bbase = abase + 16384;
            #pragma unroll
            for (int s = 0; s < 4; s++) {
                uint32_t a[2][4];
                #pragma unroll
                for (int mf = 0; mf < 2; mf++) {
                    int r = arow0 + mf * 16;
                    int u = s * 2 + ukA;
                    ldsm4(a[mf], abase + r * 128 + ((u ^ (r & 7)) << 4));
                }
                uint32_t b[8][2];
                #pragma unroll
                for (int nf4 = 0; nf4 < 4; nf4++) {
                    int r = wc * 64 + nf4 * 16 + brow_in;
                    int u = s * 2 + ukB;
                    uint32_t t[4];
                    ldsm4(t, bbase + r * 128 + ((u ^ (r & 7)) << 4));
                    b[nf4 * 2][0] = t[0]; b[nf4 * 2][1] = t[1];
                    b[nf4 * 2 + 1][0] = t[2]; b[nf4 * 2 + 1][1] = t[3];
                }
                #pragma unroll
                for (int mf = 0; mf < 2; mf++)
                    #pragma unroll
                    for (int j = 0; j < 8; j++)
                        mma16816(acc[mf][j], a[mf], b[j][0], b[j][1]);
            }
            __syncthreads();
        }

        // approx scores -> per-thread best-4 per row
        #pragma unroll
        for (int mf = 0; mf < 2; mf++) {
            #pragma unroll
            for (int h = 0; h < 2; h++) {
                const int ridx = mf * 2 + h;
                const float rrv = rrl[ridx];
                #pragma unroll
                for (int j = 0; j < 8; j++) {
                    #pragma unroll
                    for (int e = 0; e < 2; e++) {
                        int col = nb * 128 + wc * 64 + j * 8 + (lane & 3) * 2 + e;
                        float d2 = fmaf(-2.0f, acc[mf][j][h * 2 + e], rrv) + wws[col];
                        upd4(cv4 + ridx * 4, ci4 + ridx * 4, d2, col);
                    }
                }
            }
        }
    }

    // dump best-4 lists into (dead) tile smem: 128 rows x 32 slots
    float* cv = (float*)(smc + SO_TILE);
    int*   ci = (int*)(smc + SO_TILE + 16384);
    #pragma unroll
    for (int mf = 0; mf < 2; mf++)
        #pragma unroll
        for (int h = 0; h < 2; h++) {
            int row = wr * 32 + mf * 16 + g + 8 * h;
            int slot = wc * 16 + (lane & 3) * 4;
            #pragma unroll
            for (int s = 0; s < 4; s++) {
                cv[row * 32 + slot + s] = cv4[(mf * 2 + h) * 4 + s];
                ci[row * 32 + slot + s] = ci4[(mf * 2 + h) * 4 + s];
            }
        }
    __syncthreads();

    // exact rescore (reproduces the R1/reference d2 pipeline bit-for-bit)
    if (tid < BM) {
        const float* cvr = cv + tid * 32;
        const int*   cir = ci + tid * 32;
        float mv = cvr[0];
        #pragma unroll
        for (int s = 1; s < 32; s++) mv = fminf(mv, cvr[s]);
        const float band = 1e-4f;

        const float* rp = resIn + (rowbase + tid) * DDIM;
        float q[4];
        #pragma unroll
        for (int qq = 0; qq < 4; qq++) {
            float s = 0.f;
            #pragma unroll
            for (int i = 0; i < 16; i++) {
                float4 v = *(const float4*)(rp + qq * 64 + i * 4);
                s = fmaf(v.x, v.x, s); s = fmaf(v.y, v.y, s);
                s = fmaf(v.z, v.z, s); s = fmaf(v.w, v.w, s);
            }
            q[qq] = s;
        }
        float rr = ((q[0] + q[1]) + q[2]) + q[3];

        float bv = 3.0e38f; int bi = 0x7fffffff;
        for (int s = 0; s < 32; s++) {
            if (cvr[s] <= mv + band) {
                int k = cir[s];
                const float* w = cbc + (size_t)k * DDIM;
                float acc = 0.f;
                #pragma unroll 8
                for (int i = 0; i < 64; i++) {
                    float4 rv = *(const float4*)(rp + i * 4);
                    float4 wv = *(const float4*)(w + i * 4);
                    acc = fmaf(rv.x, wv.x, acc); acc = fmaf(rv.y, wv.y, acc);
                    acc = fmaf(rv.z, wv.z, acc); acc = fmaf(rv.w, wv.w, acc);
                }
                float t  = fmaf(-2.0f, acc, rr);
                float d2 = t + wws[k];
                if (d2 < bv || (d2 == bv && k < bi)) { bv = d2; bi = k; }
            }
        }
        sIdx[tid] = bi;
        if (idxOut) idxOut[(rowbase + tid) * NCB + c] = (float)bi;
    }
    __syncthreads();

    // residual / quantized / loss / next-stage split
    float* lp = qs;
    {
        int row = tid >> 1, half = tid & 1;
        size_t grow = rowbase + row;
        const float* wrow = cbc + (size_t)sIdx[row] * DDIM + half * 128;
        const float* rrow = resIn + grow * DDIM + half * 128;
        float* ro = g_res + grow * DDIM + half * 128;
        float* qo = qOut + grow * DDIM + half * 128;
        __nv_bfloat16* a1o = g_A + grow * 512 + half * 128;
        __nv_bfloat16* a2o = a1o + 256;
        float lsum = 0.f;
        #pragma unroll
        for (int i = 0; i < 32; i++) {
            float4 w4 = *(const float4*)(wrow + i * 4);
            float4 r4 = *(const float4*)(rrow + i * 4);
            float4 nr;
            nr.x = r4.x - w4.x; nr.y = r4.y - w4.y;
            nr.z = r4.z - w4.z; nr.w = r4.w - w4.w;
            *(float4*)(ro + i * 4) = nr;
            float4 qv;
            if (c == 0) qv = w4;
            else {
                float4 qp = *(const float4*)(qo + i * 4);
                qv.x = qp.x + w4.x; qv.y = qp.y + w4.y;
                qv.z = qp.z + w4.z; qv.w = qp.w + w4.w;
            }
            *(float4*)(qo + i * 4) = qv;
            lsum = fmaf(nr.x, nr.x, lsum); lsum = fmaf(nr.y, nr.y, lsum);
            lsum = fmaf(nr.z, nr.z, lsum); lsum = fmaf(nr.w, nr.w, lsum);
            if (c < 7) {
                __nv_bfloat16 p1[4], p2[4];
                split2(nr.x, p1[0], p2[0]); split2(nr.y, p1[1], p2[1]);
                split2(nr.z, p1[2], p2[2]); split2(nr.w, p1[3], p2[3]);
                *(uint64_t*)(a1o + i * 4) = *(uint64_t*)p1;
                *(uint64_t*)(a2o + i * 4) = *(uint64_t*)p2;
            }
        }
        #pragma unroll
        for (int o = 16; o; o >>= 1) lsum += __shfl_down_sync(0xffffffffu, lsum, o);
        if (lane == 0) lp[warp] = lsum;
    }
    __syncthreads();
    if (tid == 0) {
        double s = 0.0;
        #pragma unroll
        for (int w = 0; w < 8; w++) s += (double)lp[w];
        g_lp[c * NBLOCKS + blockIdx.x] = s;
    }
}

__global__ void rvq_loss_kernel(float* __restrict__ out, int lossOff)
{
    if (lossOff < 0) return;
    __shared__ double sd[256];
    int tid = threadIdx.x;
    double s = 0.0;
    for (int i = tid; i < NCB * NBLOCKS; i += 256) s += g_lp[i];
    sd[tid] = s;
    __syncthreads();
    for (int o = 128; o; o >>= 1) {
        if (tid < o) sd[tid] += sd[tid + o];
        __syncthreads();
    }
    if (tid == 0) out[lossOff] = (float)(sd[0] / (double)((long long)NROWS * DDIM));
}

extern "C" void kernel_launch(void* const* d_in, const int* in_sizes, int n_in,
                              void* d_out, int out_size)
{
    const float* z  = (const float*)d_in[0];
    const float* cb = (const float*)d_in[1];
    float* out = (float*)d_out;

    static bool attr_set = false;
    if (!attr_set) {
        cudaFuncSetAttribute(rvq_stage_kernel,
                             cudaFuncAttributeMaxDynamicSharedMemorySize, SMEMB);
        attr_set = true;
    }

    const int NZ = NROWS * DDIM, NIDX = NROWS * NCB;
    float* idxOut = nullptr;
    int lossOff = -1;
    if (out_size >= NZ + NIDX + 1) { idxOut = out + NZ; lossOff = NZ + NIDX; }
    else if (out_size == NZ + NIDX) { idxOut = out + NZ; }
    else if (out_size == NZ + 1)    { lossOff = NZ; }

    rvq_splitA_kernel<<<NROWS * 64 / 256, 256>>>(z);
    rvq_splitB_kernel<<<NCB * KCB * 64 / 256, 256>>>(cb);
    rvq_ww_kernel<<<NCB * KCB / 8, 256>>>(cb);

    for (int c = 0; c < NCB; c++)
        rvq_stage_kernel<<<NBLOCKS, TPB, SMEMB>>>(z, cb, out, idxOut, c);

    rvq_loss_kernel<<<1, 256>>>(out, lossOff);
}